// round 5
// baseline (speedup 1.0000x reference)
#include <cuda_runtime.h>
#include <cuda_bf16.h>
#include <math.h>
#include <stdint.h>

// Problem constants
#define NROWS 16384
#define NE    16384
#define D     256
#define HW    1024
#define CHW   262144

#define NT     128         // number of 128-code tiles
#define MARGIN 4e-4f
#define CAP    64

// Output layout (concatenated reference tuple, float32)
#define ZQ_OFF   0ULL
#define LOSS_OFF 4194304ULL
#define PERP_OFF 4194305ULL
#define OH_OFF   4194306ULL
#define IDX_OFF  272629762ULL

// Scratch (no device allocation allowed)
__device__ float  g_enorm[NE];
__device__ float  g_znorm[NROWS];
__device__ int    g_idx[NROWS];
__device__ int    g_count[NE];
__device__ double g_losspart[16384];
__device__ unsigned short g_ebf[NE * D];     // bf16 codebook
__device__ float  g_candv[NROWS * CAP];
__device__ int    g_candi[NROWS * CAP];
__device__ float  g_bv[NROWS];
__device__ int    g_candn[NROWS];

// ---------------------------------------------------------------------------
// Baseline-PTX helpers (no sm_103a-only instructions!)
// ---------------------------------------------------------------------------
__device__ __forceinline__ uint32_t smem_to_u32(const void* p) {
    uint32_t a;
    asm("{ .reg .u64 t; cvta.to.shared.u64 t, %1; cvt.u32.u64 %0, t; }" : "=r"(a) : "l"(p));
    return a;
}
__device__ __forceinline__ void cp_async16(uint32_t sa, const void* g) {
    asm volatile("cp.async.cg.shared.global [%0], [%1], 16;" :: "r"(sa), "l"(g));
}
#define CP_COMMIT() asm volatile("cp.async.commit_group;" ::: "memory")
#define CP_WAIT(n)  asm volatile("cp.async.wait_group %0;" :: "n"(n) : "memory")

__device__ __forceinline__ void ldm_x4(uint32_t* r, uint32_t addr) {
    asm volatile("ldmatrix.sync.aligned.m8n8.x4.shared.b16 {%0,%1,%2,%3}, [%4];"
                 : "=r"(r[0]), "=r"(r[1]), "=r"(r[2]), "=r"(r[3]) : "r"(addr));
}
__device__ __forceinline__ void mma16816(float* c, const uint32_t* a, uint32_t b0, uint32_t b1) {
    asm volatile("mma.sync.aligned.m16n8k16.row.col.f32.bf16.bf16.f32 "
                 "{%0,%1,%2,%3}, {%4,%5,%6,%7}, {%8,%9}, {%0,%1,%2,%3};"
                 : "+f"(c[0]), "+f"(c[1]), "+f"(c[2]), "+f"(c[3])
                 : "r"(a[0]), "r"(a[1]), "r"(a[2]), "r"(a[3]), "r"(b0), "r"(b1));
}

// ---------------------------------------------------------------------------
// Simple kernels
// ---------------------------------------------------------------------------
__global__ void k_zero(float* __restrict__ out, long long total) {
    float4* o4 = (float4*)(out + LOSS_OFF);
    long long n = total - (long long)LOSS_OFF;
    long long n4 = n / 4;
    long long i = (long long)blockIdx.x * blockDim.x + threadIdx.x;
    long long stride = (long long)gridDim.x * blockDim.x;
    float4 zz = make_float4(0.f, 0.f, 0.f, 0.f);
    for (long long p = i; p < n4; p += stride) o4[p] = zz;
    long long t0 = n4 * 4;
    if (i < n - t0) out[LOSS_OFF + t0 + i] = 0.f;
}

__global__ void k_zero_counts() {
    int i = blockIdx.x * blockDim.x + threadIdx.x;
    if (i < NE) g_count[i] = 0;
}

__global__ void k_e2bf(const float* __restrict__ emb) {
    int i = blockIdx.x * 256 + threadIdx.x;
    __nv_bfloat16 h = __float2bfloat16_rn(emb[i]);
    g_ebf[i] = *(unsigned short*)&h;
}

__global__ void k_enorm(const float* __restrict__ emb) {
    int r = blockIdx.x * blockDim.x + threadIdx.x;
    if (r >= NE) return;
    const float* row = emb + (size_t)r * D;
    float s = 0.f;
    for (int k = 0; k < D; k++) { float v = row[k]; s = __fadd_rn(s, __fmul_rn(v, v)); }
    g_enorm[r] = s;
}

__global__ void k_znorm(const float* __restrict__ z) {
    int r = blockIdx.x * blockDim.x + threadIdx.x;
    if (r >= NROWS) return;
    int b = r >> 10, hw = r & 1023;
    const float* base = z + (size_t)b * CHW + hw;
    float s = 0.f;
    for (int c = 0; c < D; c++) { float v = base[(size_t)c * HW]; s = __fadd_rn(s, __fmul_rn(v, v)); }
    g_znorm[r] = s;
}

// ---------------------------------------------------------------------------
// Main bf16 mma.sync GEMM + shortlist. 128 CTAs x 256 threads (8 warps 2x4).
// smem: A[128][528B] | B0[128][528B] | B1[...] | en[2][128] | S[128] | bv[128] | cnt[128]
// ---------------------------------------------------------------------------
#define PITCH 528
#define A_OFF 0
#define B_OFF 67584
#define EN_OFF (B_OFF + 2 * 67584)          // 202752
#define S_OFF  (EN_OFF + 1024)              // 203776
#define BV_OFF (S_OFF + 512)                // 204288
#define CN_OFF (BV_OFF + 512)               // 204800
#define SMEM_BYTES (CN_OFF + 512)           // 205312

__device__ __forceinline__ void load_btile(uint32_t sB, int j0, int tid) {
    #pragma unroll
    for (int l = 0; l < 16; l++) {
        int cid = l * 256 + tid;            // 4096 16B chunks
        int n   = cid >> 5;
        int c16 = cid & 31;
        cp_async16(sB + (uint32_t)n * PITCH + (uint32_t)c16 * 16,
                   g_ebf + ((size_t)(j0 + n) << 8) + c16 * 8);
    }
}

__launch_bounds__(256, 1)
__global__ void k_main(const float* __restrict__ z) {
    extern __shared__ char smem[];
    uint32_t sbase = smem_to_u32(smem);
    float* sSf  = (float*)(smem + S_OFF);
    float* enf  = (float*)(smem + EN_OFF);
    int*   sbv  = (int*)(smem + BV_OFF);
    int*   scnt = (int*)(smem + CN_OFF);

    int tid  = threadIdx.x;
    int wid  = tid >> 5;
    int lane = tid & 31;
    int wm = wid >> 2;      // 0..1
    int wn = wid & 3;       // 0..3
    int row0 = blockIdx.x * 128;
    int b0 = row0 >> 10;
    int hw0 = row0 & 1023;

    // ---- Stage A: z -> bf16 smem [m][k], pitch 528 ----
    {
        const float* zb = z + (size_t)b0 * CHW + hw0;
        int m = tid & 127;
        int chalf = (tid >> 7) * 128;
        #pragma unroll 4
        for (int cc = 0; cc < 64; cc++) {
            int c = chalf + cc * 2;
            float v0 = zb[(size_t)c * HW + m];
            float v1 = zb[(size_t)(c + 1) * HW + m];
            __nv_bfloat16 h0 = __float2bfloat16_rn(v0);
            __nv_bfloat16 h1 = __float2bfloat16_rn(v1);
            uint32_t w = (uint32_t)*(unsigned short*)&h0 | ((uint32_t)*(unsigned short*)&h1 << 16);
            *(uint32_t*)(smem + A_OFF + m * PITCH + c * 2) = w;
        }
    }
    if (tid < 128) {
        sSf[tid] = g_znorm[row0 + tid];
        sbv[tid] = 0x7f800000;              // +inf
        scnt[tid] = 0;
    }
    // first B tile + en tile
    load_btile(sbase + B_OFF, 0, tid);
    if (tid < 32) cp_async16(sbase + EN_OFF + tid * 16, g_enorm + tid * 4);
    CP_COMMIT();

    #pragma unroll 1
    for (int t = 0; t < NT; t++) {
        __syncthreads();   // everyone done reading buf (t+1)&1 from iter t-1
        int buf = t & 1;
        if (t + 1 < NT) {
            load_btile(sbase + B_OFF + (uint32_t)(buf ^ 1) * 67584, (t + 1) * 128, tid);
            if (tid < 32) cp_async16(sbase + EN_OFF + (uint32_t)(buf ^ 1) * 512 + tid * 16,
                                     g_enorm + (t + 1) * 128 + tid * 4);
            CP_COMMIT();
            CP_WAIT(1);
        } else {
            CP_WAIT(0);
        }
        __syncthreads();   // tile t visible

        // ---- 16 k-steps of mma ----
        float acc[4][4][4];
        #pragma unroll
        for (int mt = 0; mt < 4; mt++)
            #pragma unroll
            for (int nt = 0; nt < 4; nt++)
                #pragma unroll
                for (int rr = 0; rr < 4; rr++) acc[mt][nt][rr] = 0.f;

        uint32_t aBase = sbase + A_OFF + (uint32_t)(wm * 64 + (lane & 15)) * PITCH + (uint32_t)(lane >> 4) * 16;
        uint32_t bBase = sbase + B_OFF + (uint32_t)buf * 67584
                       + (uint32_t)(wn * 32 + (lane & 15)) * PITCH + (uint32_t)(lane >> 4) * 16;

        #pragma unroll
        for (int ks = 0; ks < 16; ks++) {
            uint32_t ra[4][4], rb[2][4];
            #pragma unroll
            for (int mt = 0; mt < 4; mt++)
                ldm_x4(ra[mt], aBase + (uint32_t)mt * (16 * PITCH) + (uint32_t)ks * 32);
            #pragma unroll
            for (int np = 0; np < 2; np++)
                ldm_x4(rb[np], bBase + (uint32_t)np * (16 * PITCH) + (uint32_t)ks * 32);
            #pragma unroll
            for (int mt = 0; mt < 4; mt++) {
                mma16816(acc[mt][0], ra[mt], rb[0][0], rb[0][2]);
                mma16816(acc[mt][1], ra[mt], rb[0][1], rb[0][3]);
                mma16816(acc[mt][2], ra[mt], rb[1][0], rb[1][2]);
                mma16816(acc[mt][3], ra[mt], rb[1][1], rb[1][3]);
            }
        }

        // ---- Epilogue: score + shortlist ----
        int j0 = t * 128;
        const float* enb = enf + buf * 128;
        #pragma unroll
        for (int mt = 0; mt < 4; mt++) {
            int r0 = wm * 64 + mt * 16 + (lane >> 2);
            int r1 = r0 + 8;
            float S0 = sSf[r0], S1 = sSf[r1];
            float bv0 = __int_as_float(sbv[r0]);   // stale ok (only shrinks)
            float bv1 = __int_as_float(sbv[r1]);
            #pragma unroll
            for (int nt = 0; nt < 4; nt++) {
                int cl = wn * 32 + nt * 8 + (lane & 3) * 2;
                float E0 = enb[cl], E1 = enb[cl + 1];
                #pragma unroll
                for (int e = 0; e < 2; e++) {
                    float Ee = e ? E1 : E0;
                    int   jj = j0 + cl + e;
                    float d0 = __fadd_rn(__fadd_rn(S0, Ee), __fmul_rn(-2.0f, acc[mt][nt][e]));
                    float d1 = __fadd_rn(__fadd_rn(S1, Ee), __fmul_rn(-2.0f, acc[mt][nt][2 + e]));
                    if (d0 < bv0 + MARGIN) {
                        if (d0 < bv0) { bv0 = d0; atomicMin(&sbv[r0], __float_as_int(d0)); }
                        int pos = atomicAdd(&scnt[r0], 1);
                        if (pos < CAP) {
                            g_candv[(size_t)(row0 + r0) * CAP + pos] = d0;
                            g_candi[(size_t)(row0 + r0) * CAP + pos] = jj;
                        }
                    }
                    if (d1 < bv1 + MARGIN) {
                        if (d1 < bv1) { bv1 = d1; atomicMin(&sbv[r1], __float_as_int(d1)); }
                        int pos = atomicAdd(&scnt[r1], 1);
                        if (pos < CAP) {
                            g_candv[(size_t)(row0 + r1) * CAP + pos] = d1;
                            g_candi[(size_t)(row0 + r1) * CAP + pos] = jj;
                        }
                    }
                }
            }
        }
    }
    __syncthreads();
    if (tid < 128) {
        g_bv[row0 + tid] = __int_as_float(sbv[tid]);
        g_candn[row0 + tid] = scnt[tid];
    }
}

// ---------------------------------------------------------------------------
// Exact rescore: one warp per row, bit-exact sequential fp32 chain.
// ---------------------------------------------------------------------------
__global__ void k_rescore(const float* __restrict__ z, const float* __restrict__ emb) {
    int w = (blockIdx.x * blockDim.x + threadIdx.x) >> 5;
    int lane = threadIdx.x & 31;
    if (w >= NROWS) return;
    int n = g_candn[w];
    if (n > CAP) return;                     // overflow -> fallback kernel
    float bv = g_bv[w];
    float thr = bv + MARGIN;

    // gather surviving candidates (<= 64, two slots per lane)
    float v = INFINITY; int idx = 0x7fffffff;
    int b = w >> 10, hw = w & 1023;
    const float* zr = z + (size_t)b * CHW + hw;
    float Sz = g_znorm[w];

    int nsurv = 0;
    #pragma unroll
    for (int s = 0; s < 2; s++) {
        int slot = lane + s * 32;
        bool act = (slot < n) && (g_candv[(size_t)w * CAP + slot] < thr);
        nsurv += __popc(__ballot_sync(0xffffffffu, act));
        if (act) {
            int ci = g_candi[(size_t)w * CAP + slot];
            float dd;
            // nsurv known only after both ballots; compute lazily below
            const float* er = emb + (size_t)ci * D;
            float a = 0.f;
            for (int c = 0; c < D; c++) a = fmaf(zr[(size_t)c * HW], er[c], a);
            dd = __fadd_rn(__fadd_rn(Sz, g_enorm[ci]), __fmul_rn(-2.0f, a));
            if (dd < v || (dd == v && ci < idx)) { v = dd; idx = ci; }
        }
    }
    #pragma unroll
    for (int o = 16; o; o >>= 1) {
        float vo = __shfl_xor_sync(0xffffffffu, v, o);
        int io = __shfl_xor_sync(0xffffffffu, idx, o);
        if (vo < v || (vo == v && io < idx)) { v = vo; idx = io; }
    }
    if (lane == 0) g_idx[w] = idx;
}

// Fallback: full exact scan for overflowed rows (expected: none).
__global__ void k_fallback(const float* __restrict__ z, const float* __restrict__ emb) {
    int row = blockIdx.x;
    if (g_candn[row] <= CAP) return;
    __shared__ float zrow[256];
    __shared__ float sv[256];
    __shared__ int si[256];
    int b = row >> 10, hw = row & 1023;
    const float* zr = z + (size_t)b * CHW + hw;
    zrow[threadIdx.x] = zr[(size_t)threadIdx.x * HW];
    __syncthreads();
    float S = g_znorm[row];
    float bvv = INFINITY; int bi = 0x7fffffff;
    for (int j = threadIdx.x; j < NE; j += 256) {
        const float* er = emb + (size_t)j * D;
        float acc = 0.f;
        for (int c = 0; c < D; c++) acc = fmaf(zrow[c], er[c], acc);
        float dd = __fadd_rn(__fadd_rn(S, g_enorm[j]), __fmul_rn(-2.0f, acc));
        if (dd < bvv) { bvv = dd; bi = j; }
    }
    sv[threadIdx.x] = bvv; si[threadIdx.x] = bi;
    __syncthreads();
    for (int s = 128; s; s >>= 1) {
        if (threadIdx.x < s) {
            if (sv[threadIdx.x + s] < sv[threadIdx.x] ||
                (sv[threadIdx.x + s] == sv[threadIdx.x] && si[threadIdx.x + s] < si[threadIdx.x])) {
                sv[threadIdx.x] = sv[threadIdx.x + s]; si[threadIdx.x] = si[threadIdx.x + s];
            }
        }
        __syncthreads();
    }
    if (threadIdx.x == 0) g_idx[row] = si[0];
}

// ---------------------------------------------------------------------------
__global__ void k_finalize(float* __restrict__ out) {
    int r = blockIdx.x * blockDim.x + threadIdx.x;
    if (r >= NROWS) return;
    int idx = g_idx[r];
    out[IDX_OFF + r] = (float)idx;
    out[OH_OFF + (size_t)r * NE + idx] = 1.0f;
    atomicAdd(&g_count[idx], 1);
}

__global__ void k_zq_loss(const float* __restrict__ z, const float* __restrict__ emb,
                          float* __restrict__ out) {
    int t = blockIdx.x * 256 + threadIdx.x;
    int bi = t >> 18;
    int c  = (t >> 10) & 255;
    int hw = t & 1023;
    int row = (bi << 10) + hw;
    int idx = g_idx[row];
    float e  = emb[(size_t)idx * D + c];
    float zp = z[t];
    float diff = __fadd_rn(e, -zp);
    out[ZQ_OFF + (size_t)t] = __fadd_rn(zp, diff);
    __shared__ double sd[256];
    sd[threadIdx.x] = (double)diff * (double)diff;
    __syncthreads();
    #pragma unroll
    for (int s = 128; s > 0; s >>= 1) {
        if (threadIdx.x < s) sd[threadIdx.x] += sd[threadIdx.x + s];
        __syncthreads();
    }
    if (threadIdx.x == 0) g_losspart[blockIdx.x] = sd[0];
}

__global__ void k_loss_final(float* __restrict__ out) {
    __shared__ double sd[1024];
    double s = 0.0;
    for (int i = threadIdx.x; i < 16384; i += 1024) s += g_losspart[i];
    sd[threadIdx.x] = s;
    __syncthreads();
    #pragma unroll
    for (int st = 512; st > 0; st >>= 1) {
        if (threadIdx.x < st) sd[threadIdx.x] += sd[threadIdx.x + st];
        __syncthreads();
    }
    if (threadIdx.x == 0) {
        float m = (float)(sd[0] / 4194304.0);
        out[LOSS_OFF] = __fadd_rn(m, __fmul_rn(0.25f, m));
    }
}

__global__ void k_perp(float* __restrict__ out) {
    __shared__ double sd[1024];
    double s = 0.0;
    for (int j = threadIdx.x; j < NE; j += 1024) {
        float p = (float)g_count[j] * (1.0f / 16384.0f);
        double pd = (double)p;
        s += pd * log(pd + 1e-10);
    }
    sd[threadIdx.x] = s;
    __syncthreads();
    #pragma unroll
    for (int st = 512; st > 0; st >>= 1) {
        if (threadIdx.x < st) sd[threadIdx.x] += sd[threadIdx.x + st];
        __syncthreads();
    }
    if (threadIdx.x == 0) out[PERP_OFF] = (float)exp(-sd[0]);
}

// ---------------------------------------------------------------------------
extern "C" void kernel_launch(void* const* d_in, const int* in_sizes, int n_in,
                              void* d_out, int out_size) {
    const float* z   = (const float*)d_in[0];
    const float* emb = (const float*)d_in[1];
    float* out = (float*)d_out;

    static int configured = 0;
    if (!configured) {
        cudaFuncSetAttribute(k_main, cudaFuncAttributeMaxDynamicSharedMemorySize, SMEM_BYTES);
        configured = 1;
    }

    k_zero<<<8192, 256>>>(out, (long long)out_size);
    k_zero_counts<<<64, 256>>>();
    k_e2bf<<<NE * D / 256, 256>>>(emb);
    k_enorm<<<NE / 256, 256>>>(emb);
    k_znorm<<<NROWS / 256, 256>>>(z);

    k_main<<<128, 256, SMEM_BYTES>>>(z);

    k_rescore<<<NROWS / 8, 256>>>(z, emb);
    k_fallback<<<NROWS, 256>>>(z, emb);
    k_finalize<<<NROWS / 256, 256>>>(out);
    k_zq_loss<<<(NROWS * D) / 256, 256>>>(z, emb, out);
    k_loss_final<<<1, 1024>>>(out);
    k_perp<<<1, 1024>>>(out);
}

// round 6
// speedup vs baseline: 60.0756x; 60.0756x over previous
#include <cuda_runtime.h>
#include <cuda_bf16.h>
#include <math.h>
#include <stdint.h>

// Problem constants
#define NROWS 16384
#define NE    16384
#define D     256
#define HW    1024
#define CHW   262144

#define NT     128         // number of 128-code tiles
#define MARGIN 4e-4f
#define CAP    64

// Output layout (concatenated reference tuple, float32)
#define ZQ_OFF   0ULL
#define LOSS_OFF 4194304ULL
#define PERP_OFF 4194305ULL
#define OH_OFF   4194306ULL
#define IDX_OFF  272629762ULL

// Scratch (no device allocation allowed)
__device__ float  g_enorm[NE];
__device__ float  g_znorm[NROWS];
__device__ int    g_idx[NROWS];
__device__ int    g_count[NE];
__device__ double g_losspart[16384];
__device__ unsigned short g_ebf[NE * D];     // bf16 codebook
__device__ float  g_candv[NROWS * CAP];
__device__ int    g_candi[NROWS * CAP];
__device__ float  g_bv[NROWS];
__device__ int    g_candn[NROWS];

// ---------------------------------------------------------------------------
// Baseline-PTX helpers (no sm_103a-only instructions)
// ---------------------------------------------------------------------------
__device__ __forceinline__ uint32_t smem_to_u32(const void* p) {
    uint32_t a;
    asm("{ .reg .u64 t; cvta.to.shared.u64 t, %1; cvt.u32.u64 %0, t; }" : "=r"(a) : "l"(p));
    return a;
}
__device__ __forceinline__ void cp_async16(uint32_t sa, const void* g) {
    asm volatile("cp.async.cg.shared.global [%0], [%1], 16;" :: "r"(sa), "l"(g));
}
#define CP_COMMIT() asm volatile("cp.async.commit_group;" ::: "memory")
#define CP_WAIT(n)  asm volatile("cp.async.wait_group %0;" :: "n"(n) : "memory")

__device__ __forceinline__ void ldm_x4(uint32_t* r, uint32_t addr) {
    asm volatile("ldmatrix.sync.aligned.m8n8.x4.shared.b16 {%0,%1,%2,%3}, [%4];"
                 : "=r"(r[0]), "=r"(r[1]), "=r"(r[2]), "=r"(r[3]) : "r"(addr));
}
__device__ __forceinline__ void mma16816(float* c, const uint32_t* a, uint32_t b0, uint32_t b1) {
    asm volatile("mma.sync.aligned.m16n8k16.row.col.f32.bf16.bf16.f32 "
                 "{%0,%1,%2,%3}, {%4,%5,%6,%7}, {%8,%9}, {%0,%1,%2,%3};"
                 : "+f"(c[0]), "+f"(c[1]), "+f"(c[2]), "+f"(c[3])
                 : "r"(a[0]), "r"(a[1]), "r"(a[2]), "r"(a[3]), "r"(b0), "r"(b1));
}

// ---------------------------------------------------------------------------
// Simple kernels
// ---------------------------------------------------------------------------
__global__ void k_zero(float* __restrict__ out, long long total) {
    float4* o4 = (float4*)(out + LOSS_OFF);
    long long n = total - (long long)LOSS_OFF;
    long long n4 = n / 4;
    long long i = (long long)blockIdx.x * blockDim.x + threadIdx.x;
    long long stride = (long long)gridDim.x * blockDim.x;
    float4 zz = make_float4(0.f, 0.f, 0.f, 0.f);
    for (long long p = i; p < n4; p += stride) o4[p] = zz;
    long long t0 = n4 * 4;
    if (i < n - t0) out[LOSS_OFF + t0 + i] = 0.f;
}

__global__ void k_zero_counts() {
    int i = blockIdx.x * blockDim.x + threadIdx.x;
    if (i < NE) g_count[i] = 0;
}

__global__ void k_e2bf(const float* __restrict__ emb) {
    int i = blockIdx.x * 256 + threadIdx.x;
    __nv_bfloat16 h = __float2bfloat16_rn(emb[i]);
    g_ebf[i] = *(unsigned short*)&h;
}

__global__ void k_enorm(const float* __restrict__ emb) {
    int r = blockIdx.x * blockDim.x + threadIdx.x;
    if (r >= NE) return;
    const float* row = emb + (size_t)r * D;
    float s = 0.f;
    for (int k = 0; k < D; k++) { float v = row[k]; s = __fadd_rn(s, __fmul_rn(v, v)); }
    g_enorm[r] = s;
}

__global__ void k_znorm(const float* __restrict__ z) {
    int r = blockIdx.x * blockDim.x + threadIdx.x;
    if (r >= NROWS) return;
    int b = r >> 10, hw = r & 1023;
    const float* base = z + (size_t)b * CHW + hw;
    float s = 0.f;
    for (int c = 0; c < D; c++) { float v = base[(size_t)c * HW]; s = __fadd_rn(s, __fmul_rn(v, v)); }
    g_znorm[r] = s;
}

// ---------------------------------------------------------------------------
// Main bf16 mma.sync GEMM, TWO PASSES: pass0 = exact per-row min of d_approx,
// pass1 = append candidates below bv+MARGIN. 128 CTAs x 256 threads.
// ---------------------------------------------------------------------------
#define PITCH 528
#define A_OFF 0
#define B_OFF 67584
#define EN_OFF (B_OFF + 2 * 67584)          // 202752
#define S_OFF  (EN_OFF + 1024)              // 203776
#define BV_OFF (S_OFF + 512)                // 204288
#define CN_OFF (BV_OFF + 512)               // 204800
#define SMEM_BYTES (CN_OFF + 512)           // 205312

__device__ __forceinline__ void load_btile(uint32_t sB, int j0, int tid) {
    #pragma unroll
    for (int l = 0; l < 16; l++) {
        int cid = l * 256 + tid;            // 4096 16B chunks
        int n   = cid >> 5;
        int c16 = cid & 31;
        cp_async16(sB + (uint32_t)n * PITCH + (uint32_t)c16 * 16,
                   g_ebf + ((size_t)(j0 + n) << 8) + c16 * 8);
    }
}

__device__ __forceinline__ void compute_tile(uint32_t sbase, int buf, int wm, int wn,
                                             int lane, float acc[4][4][4]) {
    #pragma unroll
    for (int mt = 0; mt < 4; mt++)
        #pragma unroll
        for (int nt = 0; nt < 4; nt++)
            #pragma unroll
            for (int rr = 0; rr < 4; rr++) acc[mt][nt][rr] = 0.f;

    uint32_t aBase = sbase + A_OFF + (uint32_t)(wm * 64 + (lane & 15)) * PITCH + (uint32_t)(lane >> 4) * 16;
    uint32_t bBase = sbase + B_OFF + (uint32_t)buf * 67584
                   + (uint32_t)(wn * 32 + (lane & 15)) * PITCH + (uint32_t)(lane >> 4) * 16;

    #pragma unroll
    for (int ks = 0; ks < 16; ks++) {
        uint32_t ra[4][4], rb[2][4];
        #pragma unroll
        for (int mt = 0; mt < 4; mt++)
            ldm_x4(ra[mt], aBase + (uint32_t)mt * (16 * PITCH) + (uint32_t)ks * 32);
        #pragma unroll
        for (int np = 0; np < 2; np++)
            ldm_x4(rb[np], bBase + (uint32_t)np * (16 * PITCH) + (uint32_t)ks * 32);
        #pragma unroll
        for (int mt = 0; mt < 4; mt++) {
            mma16816(acc[mt][0], ra[mt], rb[0][0], rb[0][2]);
            mma16816(acc[mt][1], ra[mt], rb[0][1], rb[0][3]);
            mma16816(acc[mt][2], ra[mt], rb[1][0], rb[1][2]);
            mma16816(acc[mt][3], ra[mt], rb[1][1], rb[1][3]);
        }
    }
}

__launch_bounds__(256, 1)
__global__ void k_main(const float* __restrict__ z) {
    extern __shared__ char smem[];
    uint32_t sbase = smem_to_u32(smem);
    float* sSf  = (float*)(smem + S_OFF);
    float* enf  = (float*)(smem + EN_OFF);
    int*   sbv  = (int*)(smem + BV_OFF);
    int*   scnt = (int*)(smem + CN_OFF);

    int tid  = threadIdx.x;
    int lane = tid & 31;
    int wid  = tid >> 5;
    int wm = wid >> 2;      // 0..1
    int wn = wid & 3;       // 0..3
    int row0 = blockIdx.x * 128;
    int b0 = row0 >> 10;
    int hw0 = row0 & 1023;

    // ---- Stage A: z -> bf16 smem [m][k], pitch 528 ----
    {
        const float* zb = z + (size_t)b0 * CHW + hw0;
        int m = tid & 127;
        int chalf = (tid >> 7) * 128;
        #pragma unroll 4
        for (int cc = 0; cc < 64; cc++) {
            int c = chalf + cc * 2;
            float v0 = zb[(size_t)c * HW + m];
            float v1 = zb[(size_t)(c + 1) * HW + m];
            __nv_bfloat16 h0 = __float2bfloat16_rn(v0);
            __nv_bfloat16 h1 = __float2bfloat16_rn(v1);
            uint32_t w = (uint32_t)*(unsigned short*)&h0 | ((uint32_t)*(unsigned short*)&h1 << 16);
            *(uint32_t*)(smem + A_OFF + m * PITCH + c * 2) = w;
        }
    }
    if (tid < 128) {
        sSf[tid] = g_znorm[row0 + tid];
        sbv[tid] = 0x7f800000;              // +inf
        scnt[tid] = 0;
    }
    load_btile(sbase + B_OFF, 0, tid);
    if (tid < 32) cp_async16(sbase + EN_OFF + tid * 16, g_enorm + tid * 4);
    CP_COMMIT();

    // =========================== PASS 0: min only ===========================
    float bvloc[4][2];
    #pragma unroll
    for (int mt = 0; mt < 4; mt++) { bvloc[mt][0] = INFINITY; bvloc[mt][1] = INFINITY; }

    #pragma unroll 1
    for (int t = 0; t < NT; t++) {
        __syncthreads();
        int buf = t & 1;
        if (t + 1 < NT) {
            load_btile(sbase + B_OFF + (uint32_t)(buf ^ 1) * 67584, (t + 1) * 128, tid);
            if (tid < 32) cp_async16(sbase + EN_OFF + (uint32_t)(buf ^ 1) * 512 + tid * 16,
                                     g_enorm + (t + 1) * 128 + tid * 4);
            CP_COMMIT();
            CP_WAIT(1);
        } else {
            CP_WAIT(0);
        }
        __syncthreads();

        float acc[4][4][4];
        compute_tile(sbase, buf, wm, wn, lane, acc);

        const float* enb = enf + buf * 128;
        #pragma unroll
        for (int mt = 0; mt < 4; mt++) {
            int r0 = wm * 64 + mt * 16 + (lane >> 2);
            float S0 = sSf[r0], S1 = sSf[r0 + 8];
            float b0v = bvloc[mt][0], b1v = bvloc[mt][1];
            #pragma unroll
            for (int nt = 0; nt < 4; nt++) {
                int cl = wn * 32 + nt * 8 + (lane & 3) * 2;
                float E0 = enb[cl], E1 = enb[cl + 1];
                float d00 = __fadd_rn(__fadd_rn(S0, E0), __fmul_rn(-2.0f, acc[mt][nt][0]));
                float d01 = __fadd_rn(__fadd_rn(S0, E1), __fmul_rn(-2.0f, acc[mt][nt][1]));
                float d10 = __fadd_rn(__fadd_rn(S1, E0), __fmul_rn(-2.0f, acc[mt][nt][2]));
                float d11 = __fadd_rn(__fadd_rn(S1, E1), __fmul_rn(-2.0f, acc[mt][nt][3]));
                b0v = fminf(b0v, fminf(d00, d01));
                b1v = fminf(b1v, fminf(d10, d11));
            }
            bvloc[mt][0] = b0v; bvloc[mt][1] = b1v;
        }
    }
    #pragma unroll
    for (int mt = 0; mt < 4; mt++) {
        int r0 = wm * 64 + mt * 16 + (lane >> 2);
        atomicMin(&sbv[r0],     __float_as_int(bvloc[mt][0]));   // d > 0 always
        atomicMin(&sbv[r0 + 8], __float_as_int(bvloc[mt][1]));
    }
    __syncthreads();

    float thr[4][2];
    #pragma unroll
    for (int mt = 0; mt < 4; mt++) {
        int r0 = wm * 64 + mt * 16 + (lane >> 2);
        thr[mt][0] = __int_as_float(sbv[r0]) + MARGIN;
        thr[mt][1] = __int_as_float(sbv[r0 + 8]) + MARGIN;
    }

    // reload tile 0 for pass 1
    load_btile(sbase + B_OFF, 0, tid);
    if (tid < 32) cp_async16(sbase + EN_OFF + tid * 16, g_enorm + tid * 4);
    CP_COMMIT();

    // ====================== PASS 1: append below threshold ==================
    #pragma unroll 1
    for (int t = 0; t < NT; t++) {
        __syncthreads();
        int buf = t & 1;
        if (t + 1 < NT) {
            load_btile(sbase + B_OFF + (uint32_t)(buf ^ 1) * 67584, (t + 1) * 128, tid);
            if (tid < 32) cp_async16(sbase + EN_OFF + (uint32_t)(buf ^ 1) * 512 + tid * 16,
                                     g_enorm + (t + 1) * 128 + tid * 4);
            CP_COMMIT();
            CP_WAIT(1);
        } else {
            CP_WAIT(0);
        }
        __syncthreads();

        float acc[4][4][4];
        compute_tile(sbase, buf, wm, wn, lane, acc);

        int j0 = t * 128;
        const float* enb = enf + buf * 128;
        #pragma unroll
        for (int mt = 0; mt < 4; mt++) {
            int r0 = wm * 64 + mt * 16 + (lane >> 2);
            int r1 = r0 + 8;
            float S0 = sSf[r0], S1 = sSf[r1];
            float t0 = thr[mt][0], t1 = thr[mt][1];
            #pragma unroll
            for (int nt = 0; nt < 4; nt++) {
                int cl = wn * 32 + nt * 8 + (lane & 3) * 2;
                float E0 = enb[cl], E1 = enb[cl + 1];
                #pragma unroll
                for (int e = 0; e < 2; e++) {
                    float Ee = e ? E1 : E0;
                    int   jj = j0 + cl + e;
                    float d0 = __fadd_rn(__fadd_rn(S0, Ee), __fmul_rn(-2.0f, acc[mt][nt][e]));
                    float d1 = __fadd_rn(__fadd_rn(S1, Ee), __fmul_rn(-2.0f, acc[mt][nt][2 + e]));
                    if (d0 < t0) {
                        int pos = atomicAdd(&scnt[r0], 1);
                        if (pos < CAP) {
                            g_candv[(size_t)(row0 + r0) * CAP + pos] = d0;
                            g_candi[(size_t)(row0 + r0) * CAP + pos] = jj;
                        }
                    }
                    if (d1 < t1) {
                        int pos = atomicAdd(&scnt[r1], 1);
                        if (pos < CAP) {
                            g_candv[(size_t)(row0 + r1) * CAP + pos] = d1;
                            g_candi[(size_t)(row0 + r1) * CAP + pos] = jj;
                        }
                    }
                }
            }
        }
    }
    __syncthreads();
    if (tid < 128) {
        g_bv[row0 + tid] = __int_as_float(sbv[tid]);
        g_candn[row0 + tid] = scnt[tid];
    }
}

// ---------------------------------------------------------------------------
// Exact rescore: one warp per row, bit-exact sequential fp32 chain.
// ---------------------------------------------------------------------------
__global__ void k_rescore(const float* __restrict__ z, const float* __restrict__ emb) {
    int w = (blockIdx.x * blockDim.x + threadIdx.x) >> 5;
    int lane = threadIdx.x & 31;
    if (w >= NROWS) return;
    int n = g_candn[w];
    if (n > CAP) return;                     // overflow -> fallback kernel
    float bv = g_bv[w];
    float thr = bv + MARGIN;

    float v = INFINITY; int idx = 0x7fffffff;
    int b = w >> 10, hw = w & 1023;
    const float* zr = z + (size_t)b * CHW + hw;
    float Sz = g_znorm[w];

    #pragma unroll
    for (int s = 0; s < 2; s++) {
        int slot = lane + s * 32;
        bool act = (slot < n) && (g_candv[(size_t)w * CAP + slot] < thr);
        if (act) {
            int ci = g_candi[(size_t)w * CAP + slot];
            const float* er = emb + (size_t)ci * D;
            float a = 0.f;
            for (int c = 0; c < D; c++) a = fmaf(zr[(size_t)c * HW], er[c], a);
            float dd = __fadd_rn(__fadd_rn(Sz, g_enorm[ci]), __fmul_rn(-2.0f, a));
            if (dd < v || (dd == v && ci < idx)) { v = dd; idx = ci; }
        }
    }
    #pragma unroll
    for (int o = 16; o; o >>= 1) {
        float vo = __shfl_xor_sync(0xffffffffu, v, o);
        int io = __shfl_xor_sync(0xffffffffu, idx, o);
        if (vo < v || (vo == v && io < idx)) { v = vo; idx = io; }
    }
    if (lane == 0) g_idx[w] = idx;
}

// Fallback: full exact scan for overflowed rows (expected: none).
__global__ void k_fallback(const float* __restrict__ z, const float* __restrict__ emb) {
    int row = blockIdx.x;
    if (g_candn[row] <= CAP) return;
    __shared__ float zrow[256];
    __shared__ float sv[256];
    __shared__ int si[256];
    int b = row >> 10, hw = row & 1023;
    const float* zr = z + (size_t)b * CHW + hw;
    zrow[threadIdx.x] = zr[(size_t)threadIdx.x * HW];
    __syncthreads();
    float S = g_znorm[row];
    float bvv = INFINITY; int bi = 0x7fffffff;
    for (int j = threadIdx.x; j < NE; j += 256) {
        const float* er = emb + (size_t)j * D;
        float acc = 0.f;
        for (int c = 0; c < D; c++) acc = fmaf(zrow[c], er[c], acc);
        float dd = __fadd_rn(__fadd_rn(S, g_enorm[j]), __fmul_rn(-2.0f, acc));
        if (dd < bvv) { bvv = dd; bi = j; }
    }
    sv[threadIdx.x] = bvv; si[threadIdx.x] = bi;
    __syncthreads();
    for (int s = 128; s; s >>= 1) {
        if (threadIdx.x < s) {
            if (sv[threadIdx.x + s] < sv[threadIdx.x] ||
                (sv[threadIdx.x + s] == sv[threadIdx.x] && si[threadIdx.x + s] < si[threadIdx.x])) {
                sv[threadIdx.x] = sv[threadIdx.x + s]; si[threadIdx.x] = si[threadIdx.x + s];
            }
        }
        __syncthreads();
    }
    if (threadIdx.x == 0) g_idx[row] = si[0];
}

// ---------------------------------------------------------------------------
__global__ void k_finalize(float* __restrict__ out) {
    int r = blockIdx.x * blockDim.x + threadIdx.x;
    if (r >= NROWS) return;
    int idx = g_idx[r];
    out[IDX_OFF + r] = (float)idx;
    out[OH_OFF + (size_t)r * NE + idx] = 1.0f;
    atomicAdd(&g_count[idx], 1);
}

__global__ void k_zq_loss(const float* __restrict__ z, const float* __restrict__ emb,
                          float* __restrict__ out) {
    int t = blockIdx.x * 256 + threadIdx.x;
    int bi = t >> 18;
    int c  = (t >> 10) & 255;
    int hw = t & 1023;
    int row = (bi << 10) + hw;
    int idx = g_idx[row];
    float e  = emb[(size_t)idx * D + c];
    float zp = z[t];
    float diff = __fadd_rn(e, -zp);
    out[ZQ_OFF + (size_t)t] = __fadd_rn(zp, diff);
    __shared__ double sd[256];
    sd[threadIdx.x] = (double)diff * (double)diff;
    __syncthreads();
    #pragma unroll
    for (int s = 128; s > 0; s >>= 1) {
        if (threadIdx.x < s) sd[threadIdx.x] += sd[threadIdx.x + s];
        __syncthreads();
    }
    if (threadIdx.x == 0) g_losspart[blockIdx.x] = sd[0];
}

__global__ void k_loss_final(float* __restrict__ out) {
    __shared__ double sd[1024];
    double s = 0.0;
    for (int i = threadIdx.x; i < 16384; i += 1024) s += g_losspart[i];
    sd[threadIdx.x] = s;
    __syncthreads();
    #pragma unroll
    for (int st = 512; st > 0; st >>= 1) {
        if (threadIdx.x < st) sd[threadIdx.x] += sd[threadIdx.x + st];
        __syncthreads();
    }
    if (threadIdx.x == 0) {
        float m = (float)(sd[0] / 4194304.0);
        out[LOSS_OFF] = __fadd_rn(m, __fmul_rn(0.25f, m));
    }
}

__global__ void k_perp(float* __restrict__ out) {
    __shared__ double sd[1024];
    double s = 0.0;
    for (int j = threadIdx.x; j < NE; j += 1024) {
        float p = (float)g_count[j] * (1.0f / 16384.0f);
        double pd = (double)p;
        s += pd * log(pd + 1e-10);
    }
    sd[threadIdx.x] = s;
    __syncthreads();
    #pragma unroll
    for (int st = 512; st > 0; st >>= 1) {
        if (threadIdx.x < st) sd[threadIdx.x] += sd[threadIdx.x + st];
        __syncthreads();
    }
    if (threadIdx.x == 0) out[PERP_OFF] = (float)exp(-sd[0]);
}

// ---------------------------------------------------------------------------
extern "C" void kernel_launch(void* const* d_in, const int* in_sizes, int n_in,
                              void* d_out, int out_size) {
    const float* z   = (const float*)d_in[0];
    const float* emb = (const float*)d_in[1];
    float* out = (float*)d_out;

    static int configured = 0;
    if (!configured) {
        cudaFuncSetAttribute(k_main, cudaFuncAttributeMaxDynamicSharedMemorySize, SMEM_BYTES);
        configured = 1;
    }

    k_zero<<<8192, 256>>>(out, (long long)out_size);
    k_zero_counts<<<64, 256>>>();
    k_e2bf<<<NE * D / 256, 256>>>(emb);
    k_enorm<<<NE / 256, 256>>>(emb);
    k_znorm<<<NROWS / 256, 256>>>(z);

    k_main<<<128, 256, SMEM_BYTES>>>(z);

    k_rescore<<<NROWS / 8, 256>>>(z, emb);
    k_fallback<<<NROWS, 256>>>(z, emb);
    k_finalize<<<NROWS / 256, 256>>>(out);
    k_zq_loss<<<(NROWS * D) / 256, 256>>>(z, emb, out);
    k_loss_final<<<1, 1024>>>(out);
    k_perp<<<1, 1024>>>(out);
}